// round 6
// baseline (speedup 1.0000x reference)
#include <cuda_runtime.h>

#define F_DIM 128
#define NPG   100
#define KNUM  80
#define EPG   1600
#define EPG4  (EPG / 4)   // 400 int4-groups of edges
#define TPB   256

__global__ __launch_bounds__(TPB) void sagpool_fused_kernel(
    const float* __restrict__ x,
    const int*   __restrict__ ei,      // [2, E]: [0..E) = src, [E..2E) = dst
    const float* __restrict__ theta,   // [F]
    float* __restrict__ out,
    int E, int B)
{
    __shared__ float s[NPG];            // raw dot(x_i, theta)
    __shared__ float us[NPG];           // dis_i * s_i
    __shared__ float z[NPG];            // final score
    __shared__ int   degp[8][NPG];      // per-warp src-degree histograms
    __shared__ int   hd[8][NPG];        // per-warp dst counts -> then per-warp bases
    __shared__ int   indc[NPG];         // in-degree per node
    __shared__ int   start[NPG];        // exclusive prefix of indc
    __shared__ __align__(16) int    packed[EPG];   // src | dst<<7
    __shared__ __align__(16) float  sorted[EPG];   // us[src] sorted by dst
    __shared__ uchar4 lr4a[EPG4];       // warp-local dst-rank per edge
    __shared__ float codef[NPG];        // kept ? (float)(bK+newid) : -1
    __shared__ int   inv[KNUM];
    __shared__ float scl[KNUM];
    __shared__ int   rpA[NPG];
    __shared__ int   rpB[NPG];
    __shared__ unsigned wbal[4];

    const unsigned FULL = 0xffffffffu;
    const int b     = blockIdx.x;
    const int t     = threadIdx.x;
    const int warp  = t >> 5, lane = t & 31;
    const unsigned lmlt = (1u << lane) - 1u;
    const int base  = b * NPG;
    const int ebase = b * EPG;
    const int bK    = b * KNUM;

    // zero both histogram banks (visible after the post-A barrier)
    for (int i = t; i < 8 * NPG; i += TPB) { (&degp[0][0])[i] = 0; (&hd[0][0])[i] = 0; }

    // ================= Phase A: warp-specialized =================
    if (warp < 4) {
        // warps 0-3: 100 dot products, 4 rows in flight; theta straight from global
        float4 tv = reinterpret_cast<const float4*>(theta)[lane];
        #pragma unroll
        for (int gb = 0; gb < 24; gb += 4) {
            float d[4];
            #pragma unroll
            for (int c = 0; c < 4; c++) {
                int i = warp + 4 * (gb + c);
                float4 v = reinterpret_cast<const float4*>(x + (size_t)(base + i) * F_DIM)[lane];
                d[c] = v.x * tv.x + v.y * tv.y + v.z * tv.z + v.w * tv.w;
            }
            #pragma unroll
            for (int o = 16; o > 0; o >>= 1) {
                #pragma unroll
                for (int c = 0; c < 4; c++) d[c] += __shfl_down_sync(FULL, d[c], o);
            }
            if (lane == 0) {
                #pragma unroll
                for (int c = 0; c < 4; c++) s[warp + 4 * (gb + c)] = d[c];
            }
        }
        {   // leftover row
            int i = warp + 96;
            float4 v = reinterpret_cast<const float4*>(x + (size_t)(base + i) * F_DIM)[lane];
            float d = v.x * tv.x + v.y * tv.y + v.z * tv.z + v.w * tv.w;
            #pragma unroll
            for (int o = 16; o > 0; o >>= 1) d += __shfl_down_sync(FULL, d, o);
            if (lane == 0) s[i] = d;
        }
    } else {
        // warps 4-7: load edges, pack into one word each
        const int tt = t - 128;
        const int4* src4 = reinterpret_cast<const int4*>(ei + ebase);
        const int4* dst4 = reinterpret_cast<const int4*>(ei + (size_t)E + ebase);
        #pragma unroll
        for (int q0 = 0; q0 < EPG4; q0 += 128) {
            int q = q0 + tt;
            if (q < EPG4) {
                int4 sv = src4[q]; int4 dv = dst4[q];
                int4 pk;
                pk.x = (sv.x - base) | ((dv.x - base) << 7);
                pk.y = (sv.y - base) | ((dv.y - base) << 7);
                pk.z = (sv.z - base) | ((dv.z - base) << 7);
                pk.w = (sv.w - base) | ((dv.w - base) << 7);
                reinterpret_cast<int4*>(packed)[q] = pk;
            }
        }
    }
    __syncthreads();

    // ================= Phase B: match-based histograms + dst-rank (no atomics) =================
    // warp w owns int4 indices [w*50, w*50+50) -> 200 edges per warp (rank fits uint8)
    {
        const int wq0 = warp * 50;
        #pragma unroll
        for (int rdx = 0; rdx < 2; rdx++) {
            int i = lane + rdx * 32;
            int q = wq0 + i;
            unsigned act = __ballot_sync(FULL, i < 50);
            if (i < 50) {
                int4 pk = reinterpret_cast<const int4*>(packed)[q];
                int sls[4] = { pk.x & 127, pk.y & 127, pk.z & 127, pk.w & 127 };
                int dls[4] = { (pk.x >> 7) & 127, (pk.y >> 7) & 127,
                               (pk.z >> 7) & 127, (pk.w >> 7) & 127 };
                unsigned char lrs[4];
                #pragma unroll
                for (int c = 0; c < 4; c++) {
                    // src histogram (degree)
                    unsigned g1 = __match_any_sync(act, sls[c]);
                    if ((g1 & lmlt) == 0) degp[warp][sls[c]] += __popc(g1);
                    // dst count + warp-local rank
                    unsigned g2 = __match_any_sync(act, dls[c]);
                    int ldr = __ffs(g2) - 1;
                    int rk  = __popc(g2 & lmlt);
                    int old = 0;
                    if (rk == 0) old = hd[warp][dls[c]];
                    old = __shfl_sync(act, old, ldr);
                    lrs[c] = (unsigned char)(old + rk);
                    if (rk == 0) hd[warp][dls[c]] = old + __popc(g2);
                }
                lr4a[q] = make_uchar4(lrs[0], lrs[1], lrs[2], lrs[3]);
            }
        }
    }
    __syncthreads();

    // ================= Phase C (concurrent): scan+bases (warp 0) || deg/us (warps 4-7) ===
    float dis_r = 0.0f, self_r = 0.0f;
    if (warp == 0) {
        // exclusive scan of in-degree + per-warp base offsets
        int n0 = lane * 4;
        int tot[4]; int LS = 0;
        if (lane < 25) {
            #pragma unroll
            for (int k = 0; k < 4; k++) {
                int tt2 = 0;
                #pragma unroll
                for (int w = 0; w < 8; w++) tt2 += hd[w][n0 + k];
                tot[k] = tt2; LS += tt2;
            }
        }
        int pre = LS;
        #pragma unroll
        for (int o = 1; o < 32; o <<= 1) {
            int v = __shfl_up_sync(FULL, pre, o);
            if (lane >= o) pre += v;
        }
        pre -= LS;   // exclusive
        if (lane < 25) {
            int a0 = pre;
            #pragma unroll
            for (int k = 0; k < 4; k++) {
                int n = n0 + k;
                start[n] = a0; indc[n] = tot[k];
                int a = a0;
                #pragma unroll
                for (int w = 0; w < 8; w++) { int c = hd[w][n]; hd[w][n] = a; a += c; }
                a0 += tot[k];
            }
        }
    } else if (t >= 128 && t < 128 + NPG) {
        int tt = t - 128;
        int deg = 1;
        #pragma unroll
        for (int w = 0; w < 8; w++) deg += degp[w][tt];
        float fd = (float)deg;
        float dr = rsqrtf(fd);
        float sv = s[tt];
        us[tt]  = dr * sv;
        dis_r   = dr;
        self_r  = sv / fd;
    }
    __syncthreads();

    // ================= Phase D: placement (plain STS, unique positions) =================
    #pragma unroll
    for (int rdx = 0; rdx < 2; rdx++) {
        int q = t + rdx * 256;
        if (q < EPG4) {
            int4 pk = reinterpret_cast<const int4*>(packed)[q];
            uchar4 lr = lr4a[q];
            int we = q / 50;            // warp that ranked this edge group
            const int* hb = hd[we];
            sorted[hb[(pk.x >> 7) & 127] + lr.x] = us[pk.x & 127];
            sorted[hb[(pk.y >> 7) & 127] + lr.y] = us[pk.y & 127];
            sorted[hb[(pk.z >> 7) & 127] + lr.z] = us[pk.z & 127];
            sorted[hb[(pk.w >> 7) & 127] + lr.w] = us[pk.w & 127];
        }
    }
    __syncthreads();

    // ================= Phase E: per-node gather -> z =================
    if (t >= 128 && t < 128 + NPG) {
        int tt = t - 128;
        int st = start[tt], ic = indc[tt];
        float sum = 0.0f;
        for (int j = 0; j < ic; j++) sum += sorted[st + j];
        z[tt] = self_r + dis_r * sum;
    }
    __syncthreads();

    // ================= rank counting, split j-halves =================
    if (t < NPG) {
        float zi = z[t]; int r = 0;
        #pragma unroll 5
        for (int j = 0; j < NPG / 2; j++) {
            float zj = z[j];
            r += (zj > zi) || (zj == zi && j < t);
        }
        rpA[t] = r;
    } else if (t >= 128 && t < 128 + NPG) {
        int i = t - 128;
        float zi = z[i]; int r = 0;
        #pragma unroll 5
        for (int j = NPG / 2; j < NPG; j++) {
            float zj = z[j];
            r += (zj > zi) || (zj == zi && j < i);
        }
        rpB[i] = r;
    }
    __syncthreads();

    // ================= kept flags + ballots =================
    int k = 0;
    if (t < 128) {
        k = (t < NPG) ? ((rpA[t] + rpB[t]) < KNUM) : 0;
        unsigned bal = __ballot_sync(FULL, k);
        if (lane == 0) wbal[warp] = bal;
    }
    __syncthreads();

    // ================= scan -> codef, inv, scl =================
    if (t < NPG) {
        int off = __popc(wbal[warp] & lmlt);
        #pragma unroll
        for (int w = 0; w < 4; w++) if (w < warp) off += __popc(wbal[w]);
        codef[t] = k ? (float)(bK + off) : -1.0f;
        if (k) {
            inv[off] = t;
            scl[off] = 1.0f / (1.0f + __expf(-z[t]));
        }
    }
    __syncthreads();

    // ================= outputs: [x_new | edge0 | edge1 | batch] =================
    const size_t EOUT0 = (size_t)B * KNUM * F_DIM;
    const size_t EOUT1 = EOUT0 + (size_t)E;
    const size_t BOUT  = EOUT0 + 2 * (size_t)E;

    for (int r = warp; r < KNUM; r += 8) {
        int i = inv[r];
        float sc = scl[r];
        float4 v = reinterpret_cast<const float4*>(x + (size_t)(base + i) * F_DIM)[lane];
        v.x *= sc; v.y *= sc; v.z *= sc; v.w *= sc;
        reinterpret_cast<float4*>(out + (size_t)(bK + r) * F_DIM)[lane] = v;
    }

    if (t < KNUM) out[BOUT + (size_t)bK + t] = (float)b;

    float4* e0out = reinterpret_cast<float4*>(out + EOUT0 + ebase);
    float4* e1out = reinterpret_cast<float4*>(out + EOUT1 + ebase);
    for (int q = t; q < EPG4; q += TPB) {
        int4 pk = reinterpret_cast<const int4*>(packed)[q];
        float4 o0, o1;
        float cs, cd;
        cs = codef[pk.x & 127]; cd = codef[(pk.x >> 7) & 127];
        o0.x = (cd < 0.0f) ? -1.0f : cs;  o1.x = (cs < 0.0f) ? -1.0f : cd;
        cs = codef[pk.y & 127]; cd = codef[(pk.y >> 7) & 127];
        o0.y = (cd < 0.0f) ? -1.0f : cs;  o1.y = (cs < 0.0f) ? -1.0f : cd;
        cs = codef[pk.z & 127]; cd = codef[(pk.z >> 7) & 127];
        o0.z = (cd < 0.0f) ? -1.0f : cs;  o1.z = (cs < 0.0f) ? -1.0f : cd;
        cs = codef[pk.w & 127]; cd = codef[(pk.w >> 7) & 127];
        o0.w = (cd < 0.0f) ? -1.0f : cs;  o1.w = (cs < 0.0f) ? -1.0f : cd;
        e0out[q] = o0;
        e1out[q] = o1;
    }
}

extern "C" void kernel_launch(void* const* d_in, const int* in_sizes, int n_in,
                              void* d_out, int out_size)
{
    const float* x     = (const float*)d_in[0];
    const int*   ei    = (const int*)d_in[1];
    const float* theta = (const float*)d_in[3];
    float* out = (float*)d_out;

    int N = in_sizes[0] / F_DIM;   // 100000
    int E = in_sizes[1] / 2;       // 1600000
    int B = N / NPG;               // 1000

    sagpool_fused_kernel<<<B, TPB>>>(x, ei, theta, out, E, B);
}

// round 7
// speedup vs baseline: 1.0353x; 1.0353x over previous
#include <cuda_runtime.h>

#define F_DIM 128
#define NPG   100
#define KNUM  80
#define EPG   1600
#define EPG4  (EPG / 4)   // 400 int4 groups
#define TPB   256

__global__ __launch_bounds__(TPB, 8) void sagpool_fused_kernel(
    const float* __restrict__ x,
    const int*   __restrict__ ei,      // [2, E]: [0..E) = src, [E..2E) = dst
    const float* __restrict__ theta,   // [F]
    float* __restrict__ out,
    int E, int B)
{
    __shared__ float s[NPG];           // dot(x_i, theta); later self-loop term
    __shared__ float us[NPG];          // dis_i * s_i
    __shared__ float z[NPG];           // scatter accumulator -> final score
    __shared__ float dis[NPG];
    __shared__ int   degp[4][NPG];     // per-warp (warps 4..7) degree hists
    __shared__ __align__(16) int packed[EPG];   // (src-base) | (dst-base)<<7
    __shared__ float codef[NPG];       // kept ? (float)(bK+newid) : -1
    __shared__ int   inv[KNUM];
    __shared__ float scl[KNUM];
    __shared__ int   rpA[NPG];
    __shared__ int   rpB[NPG];
    __shared__ unsigned wbal[4];

    const unsigned FULL = 0xffffffffu;
    const int b     = blockIdx.x;
    const int t     = threadIdx.x;
    const int warp  = t >> 5, lane = t & 31;
    const int base  = b * NPG;
    const int ebase = b * EPG;
    const int bK    = b * KNUM;

    // ================= Phase A: warp-specialized =================
    if (warp < 4) {
        // warps 0-3: 100 dot products, 4 rows in flight; theta from global (L2 bcast)
        float4 tv = reinterpret_cast<const float4*>(theta)[lane];
        #pragma unroll
        for (int gb = 0; gb < 24; gb += 4) {
            float d[4];
            #pragma unroll
            for (int c = 0; c < 4; c++) {
                int i = warp + 4 * (gb + c);
                float4 v = reinterpret_cast<const float4*>(x + (size_t)(base + i) * F_DIM)[lane];
                d[c] = v.x * tv.x + v.y * tv.y + v.z * tv.z + v.w * tv.w;
            }
            #pragma unroll
            for (int o = 16; o > 0; o >>= 1) {
                #pragma unroll
                for (int c = 0; c < 4; c++) d[c] += __shfl_down_sync(FULL, d[c], o);
            }
            if (lane == 0) {
                #pragma unroll
                for (int c = 0; c < 4; c++) s[warp + 4 * (gb + c)] = d[c];
            }
        }
        {   // leftover row
            int i = warp + 96;
            float4 v = reinterpret_cast<const float4*>(x + (size_t)(base + i) * F_DIM)[lane];
            float d = v.x * tv.x + v.y * tv.y + v.z * tv.z + v.w * tv.w;
            #pragma unroll
            for (int o = 16; o > 0; o >>= 1) d += __shfl_down_sync(FULL, d, o);
            if (lane == 0) s[i] = d;
        }
    } else {
        // warps 4-7: init z + hist, load+pack edges, match-based degree histogram
        const int w  = warp - 4;
        const int tt = t - 128;            // 0..127
        for (int i = lane; i < NPG; i += 32) {
            degp[w][i] = 0;
            if (w == 0) z[i] = 0.0f;
        }
        __syncwarp();

        const int4* src4 = reinterpret_cast<const int4*>(ei + ebase);
        const int4* dst4 = reinterpret_cast<const int4*>(ei + (size_t)E + ebase);
        #pragma unroll
        for (int q0 = 0; q0 < EPG4; q0 += 128) {
            int q = q0 + tt;
            unsigned act = __ballot_sync(FULL, q < EPG4);
            if (q < EPG4) {
                int4 sv = src4[q]; int4 dv = dst4[q];
                int4 pk;
                pk.x = (sv.x - base) | ((dv.x - base) << 7);
                pk.y = (sv.y - base) | ((dv.y - base) << 7);
                pk.z = (sv.z - base) | ((dv.z - base) << 7);
                pk.w = (sv.w - base) | ((dv.w - base) << 7);
                reinterpret_cast<int4*>(packed)[q] = pk;
                int vals[4] = { pk.x & 127, pk.y & 127, pk.z & 127, pk.w & 127 };
                #pragma unroll
                for (int c = 0; c < 4; c++) {
                    unsigned grp = __match_any_sync(act, vals[c]);
                    if ((grp & ((1u << lane) - 1u)) == 0)
                        degp[w][vals[c]] += __popc(grp);
                }
            }
        }
    }
    __syncthreads();

    // ================= per-node: deg, dis, us, self term =================
    if (t < NPG) {
        int d = 1 + degp[0][t] + degp[1][t] + degp[2][t] + degp[3][t];
        float fd = (float)d;
        float r  = rsqrtf(fd);
        float sv = s[t];
        dis[t] = r;
        us[t]  = r * sv;
        s[t]   = sv / fd;
    }
    __syncthreads();

    // ================= z[dst] += dis[src]*s[src] : two static blocks =================
    {
        int4 pkA = reinterpret_cast<const int4*>(packed)[t];
        bool hasB = (t + 256) < EPG4;
        int4 pkB = hasB ? reinterpret_cast<const int4*>(packed)[t + 256] : make_int4(0,0,0,0);

        atomicAdd(&z[(pkA.x >> 7) & 127], us[pkA.x & 127]);
        atomicAdd(&z[(pkA.y >> 7) & 127], us[pkA.y & 127]);
        atomicAdd(&z[(pkA.z >> 7) & 127], us[pkA.z & 127]);
        atomicAdd(&z[(pkA.w >> 7) & 127], us[pkA.w & 127]);
        if (hasB) {
            atomicAdd(&z[(pkB.x >> 7) & 127], us[pkB.x & 127]);
            atomicAdd(&z[(pkB.y >> 7) & 127], us[pkB.y & 127]);
            atomicAdd(&z[(pkB.z >> 7) & 127], us[pkB.z & 127]);
            atomicAdd(&z[(pkB.w >> 7) & 127], us[pkB.w & 127]);
        }
    }
    __syncthreads();

    if (t < NPG) z[t] = s[t] + dis[t] * z[t];
    __syncthreads();

    // ================= rank counting, split j-halves =================
    if (t < NPG) {
        float zi = z[t]; int r = 0;
        #pragma unroll 5
        for (int j = 0; j < NPG / 2; j++) {
            float zj = z[j];
            r += (zj > zi) || (zj == zi && j < t);
        }
        rpA[t] = r;
    } else if (t >= 128 && t < 128 + NPG) {
        int i = t - 128;
        float zi = z[i]; int r = 0;
        #pragma unroll 5
        for (int j = NPG / 2; j < NPG; j++) {
            float zj = z[j];
            r += (zj > zi) || (zj == zi && j < i);
        }
        rpB[i] = r;
    }
    __syncthreads();

    // ================= kept flags (registers) + ballots =================
    int k = 0;
    if (t < 128) {
        k = (t < NPG) ? ((rpA[t] + rpB[t]) < KNUM) : 0;
        unsigned bal = __ballot_sync(FULL, k);
        if (lane == 0) wbal[warp] = bal;
    }
    __syncthreads();

    // ================= scan -> codef, inv, scl =================
    if (t < NPG) {
        int off = __popc(wbal[warp] & ((1u << lane) - 1u));
        #pragma unroll
        for (int w = 0; w < 4; w++) if (w < warp) off += __popc(wbal[w]);
        codef[t] = k ? (float)(bK + off) : -1.0f;
        if (k) {
            inv[off] = t;
            scl[off] = 1.0f / (1.0f + __expf(-z[t]));
        }
    }
    __syncthreads();

    // ================= outputs: [x_new | edge0 | edge1 | batch] =================
    const size_t EOUT0 = (size_t)B * KNUM * F_DIM;
    const size_t EOUT1 = EOUT0 + (size_t)E;
    const size_t BOUT  = EOUT0 + 2 * (size_t)E;

    // x_new: 10 rows per warp, unrolled x2 (two LDG.128 in flight)
    #pragma unroll
    for (int rr = 0; rr < 10; rr += 2) {
        int r0 = warp + 8 * rr, r1 = warp + 8 * (rr + 1);
        int i0 = inv[r0],       i1 = inv[r1];
        float sc0 = scl[r0],    sc1 = scl[r1];
        float4 v0 = reinterpret_cast<const float4*>(x + (size_t)(base + i0) * F_DIM)[lane];
        float4 v1 = reinterpret_cast<const float4*>(x + (size_t)(base + i1) * F_DIM)[lane];
        v0.x *= sc0; v0.y *= sc0; v0.z *= sc0; v0.w *= sc0;
        v1.x *= sc1; v1.y *= sc1; v1.z *= sc1; v1.w *= sc1;
        reinterpret_cast<float4*>(out + (size_t)(bK + r0) * F_DIM)[lane] = v0;
        reinterpret_cast<float4*>(out + (size_t)(bK + r1) * F_DIM)[lane] = v1;
    }

    if (t < KNUM) out[BOUT + (size_t)bK + t] = (float)b;

    // relabeled edges via codef: two static blocks
    float4* e0out = reinterpret_cast<float4*>(out + EOUT0 + ebase);
    float4* e1out = reinterpret_cast<float4*>(out + EOUT1 + ebase);
    {
        int4 pk = reinterpret_cast<const int4*>(packed)[t];
        float4 o0, o1; float cs, cd;
        cs = codef[pk.x & 127]; cd = codef[(pk.x >> 7) & 127];
        o0.x = (cd < 0.0f) ? -1.0f : cs;  o1.x = (cs < 0.0f) ? -1.0f : cd;
        cs = codef[pk.y & 127]; cd = codef[(pk.y >> 7) & 127];
        o0.y = (cd < 0.0f) ? -1.0f : cs;  o1.y = (cs < 0.0f) ? -1.0f : cd;
        cs = codef[pk.z & 127]; cd = codef[(pk.z >> 7) & 127];
        o0.z = (cd < 0.0f) ? -1.0f : cs;  o1.z = (cs < 0.0f) ? -1.0f : cd;
        cs = codef[pk.w & 127]; cd = codef[(pk.w >> 7) & 127];
        o0.w = (cd < 0.0f) ? -1.0f : cs;  o1.w = (cs < 0.0f) ? -1.0f : cd;
        e0out[t] = o0;
        e1out[t] = o1;
    }
    if (t + 256 < EPG4) {
        int q = t + 256;
        int4 pk = reinterpret_cast<const int4*>(packed)[q];
        float4 o0, o1; float cs, cd;
        cs = codef[pk.x & 127]; cd = codef[(pk.x >> 7) & 127];
        o0.x = (cd < 0.0f) ? -1.0f : cs;  o1.x = (cs < 0.0f) ? -1.0f : cd;
        cs = codef[pk.y & 127]; cd = codef[(pk.y >> 7) & 127];
        o0.y = (cd < 0.0f) ? -1.0f : cs;  o1.y = (cs < 0.0f) ? -1.0f : cd;
        cs = codef[pk.z & 127]; cd = codef[(pk.z >> 7) & 127];
        o0.z = (cd < 0.0f) ? -1.0f : cs;  o1.z = (cs < 0.0f) ? -1.0f : cd;
        cs = codef[pk.w & 127]; cd = codef[(pk.w >> 7) & 127];
        o0.w = (cd < 0.0f) ? -1.0f : cs;  o1.w = (cs < 0.0f) ? -1.0f : cd;
        e0out[q] = o0;
        e1out[q] = o1;
    }
}

extern "C" void kernel_launch(void* const* d_in, const int* in_sizes, int n_in,
                              void* d_out, int out_size)
{
    const float* x     = (const float*)d_in[0];
    const int*   ei    = (const int*)d_in[1];
    const float* theta = (const float*)d_in[3];
    float* out = (float*)d_out;

    int N = in_sizes[0] / F_DIM;   // 100000
    int E = in_sizes[1] / 2;       // 1600000
    int B = N / NPG;               // 1000

    sagpool_fused_kernel<<<B, TPB>>>(x, ei, theta, out, E, B);
}

// round 8
// speedup vs baseline: 1.5529x; 1.5000x over previous
#include <cuda_runtime.h>

#define F_DIM 128
#define NPG   100
#define KNUM  80
#define EPG   1600
#define EPG4  (EPG / 4)   // 400 int4 groups
#define TPB   256

__global__ __launch_bounds__(TPB, 8) void sagpool_fused_kernel(
    const float* __restrict__ x,
    const int*   __restrict__ ei,      // [2, E]: [0..E) = src, [E..2E) = dst
    const float* __restrict__ theta,   // [F]
    float* __restrict__ out,
    int E, int B)
{
    __shared__ float s[NPG];           // dot(x_i, theta); later self-loop term
    __shared__ float us[NPG];          // dis_i * s_i
    __shared__ float z[NPG];           // scatter accumulator -> final score
    __shared__ float dis[NPG];
    __shared__ int   degp[4][NPG];     // per-warp (warps 4..7) degree hists
    __shared__ __align__(16) int packed[EPG];   // (src-base) | (dst-base)<<7
    __shared__ float codef[NPG];       // kept ? (float)(bK+newid) : -1
    __shared__ int   inv[KNUM];
    __shared__ float scl[KNUM];
    __shared__ int   rpA[NPG];
    __shared__ int   rpB[NPG];
    __shared__ unsigned wbal[4];

    const unsigned FULL = 0xffffffffu;
    const int b     = blockIdx.x;
    const int t     = threadIdx.x;
    const int warp  = t >> 5, lane = t & 31;
    const int base  = b * NPG;
    const int ebase = b * EPG;
    const int bK    = b * KNUM;

    // ================= Phase A: warp-specialized =================
    if (warp < 4) {
        // warps 0-3: 100 dot products, 4 rows in flight; theta from global (L2 bcast)
        float4 tv = reinterpret_cast<const float4*>(theta)[lane];
        #pragma unroll
        for (int gb = 0; gb < 24; gb += 4) {
            float d[4];
            #pragma unroll
            for (int c = 0; c < 4; c++) {
                int i = warp + 4 * (gb + c);
                float4 v = reinterpret_cast<const float4*>(x + (size_t)(base + i) * F_DIM)[lane];
                d[c] = v.x * tv.x + v.y * tv.y + v.z * tv.z + v.w * tv.w;
            }
            #pragma unroll
            for (int o = 16; o > 0; o >>= 1) {
                #pragma unroll
                for (int c = 0; c < 4; c++) d[c] += __shfl_down_sync(FULL, d[c], o);
            }
            if (lane == 0) {
                #pragma unroll
                for (int c = 0; c < 4; c++) s[warp + 4 * (gb + c)] = d[c];
            }
        }
        {   // leftover row
            int i = warp + 96;
            float4 v = reinterpret_cast<const float4*>(x + (size_t)(base + i) * F_DIM)[lane];
            float d = v.x * tv.x + v.y * tv.y + v.z * tv.z + v.w * tv.w;
            #pragma unroll
            for (int o = 16; o > 0; o >>= 1) d += __shfl_down_sync(FULL, d, o);
            if (lane == 0) s[i] = d;
        }
    } else {
        // warps 4-7: init z + hist, load+pack edges, match-based degree histogram
        const int w  = warp - 4;
        const int tt = t - 128;            // 0..127
        for (int i = lane; i < NPG; i += 32) {
            degp[w][i] = 0;
            if (w == 0) z[i] = 0.0f;
        }
        __syncwarp();

        const int4* src4 = reinterpret_cast<const int4*>(ei + ebase);
        const int4* dst4 = reinterpret_cast<const int4*>(ei + (size_t)E + ebase);
        #pragma unroll
        for (int q0 = 0; q0 < EPG4; q0 += 128) {
            int q = q0 + tt;
            unsigned act = __ballot_sync(FULL, q < EPG4);
            if (q < EPG4) {
                int4 sv = src4[q]; int4 dv = dst4[q];
                int4 pk;
                pk.x = (sv.x - base) | ((dv.x - base) << 7);
                pk.y = (sv.y - base) | ((dv.y - base) << 7);
                pk.z = (sv.z - base) | ((dv.z - base) << 7);
                pk.w = (sv.w - base) | ((dv.w - base) << 7);
                reinterpret_cast<int4*>(packed)[q] = pk;
                int vals[4] = { pk.x & 127, pk.y & 127, pk.z & 127, pk.w & 127 };
                #pragma unroll
                for (int c = 0; c < 4; c++) {
                    unsigned grp = __match_any_sync(act, vals[c]);
                    if ((grp & ((1u << lane) - 1u)) == 0)
                        degp[w][vals[c]] += __popc(grp);
                }
            }
        }
    }
    __syncthreads();

    // ================= per-node: deg, dis, us, self term =================
    if (t < NPG) {
        int d = 1 + degp[0][t] + degp[1][t] + degp[2][t] + degp[3][t];
        float fd = (float)d;
        float r  = rsqrtf(fd);
        float sv = s[t];
        dis[t] = r;
        us[t]  = r * sv;
        s[t]   = sv / fd;
    }
    __syncthreads();

    // ================= z[dst] += dis[src]*s[src] : two static blocks =================
    {
        int4 pkA = reinterpret_cast<const int4*>(packed)[t];
        bool hasB = (t + 256) < EPG4;
        int4 pkB = hasB ? reinterpret_cast<const int4*>(packed)[t + 256] : make_int4(0,0,0,0);

        atomicAdd(&z[(pkA.x >> 7) & 127], us[pkA.x & 127]);
        atomicAdd(&z[(pkA.y >> 7) & 127], us[pkA.y & 127]);
        atomicAdd(&z[(pkA.z >> 7) & 127], us[pkA.z & 127]);
        atomicAdd(&z[(pkA.w >> 7) & 127], us[pkA.w & 127]);
        if (hasB) {
            atomicAdd(&z[(pkB.x >> 7) & 127], us[pkB.x & 127]);
            atomicAdd(&z[(pkB.y >> 7) & 127], us[pkB.y & 127]);
            atomicAdd(&z[(pkB.z >> 7) & 127], us[pkB.z & 127]);
            atomicAdd(&z[(pkB.w >> 7) & 127], us[pkB.w & 127]);
        }
    }
    __syncthreads();

    if (t < NPG) z[t] = s[t] + dis[t] * z[t];
    __syncthreads();

    // ================= rank counting, split j-halves =================
    if (t < NPG) {
        float zi = z[t]; int r = 0;
        #pragma unroll 5
        for (int j = 0; j < NPG / 2; j++) {
            float zj = z[j];
            r += (zj > zi) || (zj == zi && j < t);
        }
        rpA[t] = r;
    } else if (t >= 128 && t < 128 + NPG) {
        int i = t - 128;
        float zi = z[i]; int r = 0;
        #pragma unroll 5
        for (int j = NPG / 2; j < NPG; j++) {
            float zj = z[j];
            r += (zj > zi) || (zj == zi && j < i);
        }
        rpB[i] = r;
    }
    __syncthreads();

    // ================= kept flags (registers) + ballots =================
    int k = 0;
    if (t < 128) {
        k = (t < NPG) ? ((rpA[t] + rpB[t]) < KNUM) : 0;
        unsigned bal = __ballot_sync(FULL, k);
        if (lane == 0) wbal[warp] = bal;
    }
    __syncthreads();

    // ================= scan -> codef, inv, scl =================
    if (t < NPG) {
        int off = __popc(wbal[warp] & ((1u << lane) - 1u));
        #pragma unroll
        for (int w = 0; w < 4; w++) if (w < warp) off += __popc(wbal[w]);
        codef[t] = k ? (float)(bK + off) : -1.0f;
        if (k) {
            inv[off] = t;
            scl[off] = 1.0f / (1.0f + __expf(-z[t]));
        }
    }
    __syncthreads();

    // ================= outputs: [x_new | edge0 | edge1 | batch] =================
    const size_t EOUT0 = (size_t)B * KNUM * F_DIM;
    const size_t EOUT1 = EOUT0 + (size_t)E;
    const size_t BOUT  = EOUT0 + 2 * (size_t)E;

    // x_new: 10 rows per warp, unrolled x2 (two LDG.128 in flight)
    #pragma unroll
    for (int rr = 0; rr < 10; rr += 2) {
        int r0 = warp + 8 * rr, r1 = warp + 8 * (rr + 1);
        int i0 = inv[r0],       i1 = inv[r1];
        float sc0 = scl[r0],    sc1 = scl[r1];
        float4 v0 = reinterpret_cast<const float4*>(x + (size_t)(base + i0) * F_DIM)[lane];
        float4 v1 = reinterpret_cast<const float4*>(x + (size_t)(base + i1) * F_DIM)[lane];
        v0.x *= sc0; v0.y *= sc0; v0.z *= sc0; v0.w *= sc0;
        v1.x *= sc1; v1.y *= sc1; v1.z *= sc1; v1.w *= sc1;
        reinterpret_cast<float4*>(out + (size_t)(bK + r0) * F_DIM)[lane] = v0;
        reinterpret_cast<float4*>(out + (size_t)(bK + r1) * F_DIM)[lane] = v1;
    }

    if (t < KNUM) out[BOUT + (size_t)bK + t] = (float)b;

    // relabeled edges via codef: two static blocks
    float4* e0out = reinterpret_cast<float4*>(out + EOUT0 + ebase);
    float4* e1out = reinterpret_cast<float4*>(out + EOUT1 + ebase);
    {
        int4 pk = reinterpret_cast<const int4*>(packed)[t];
        float4 o0, o1; float cs, cd;
        cs = codef[pk.x & 127]; cd = codef[(pk.x >> 7) & 127];
        o0.x = (cd < 0.0f) ? -1.0f : cs;  o1.x = (cs < 0.0f) ? -1.0f : cd;
        cs = codef[pk.y & 127]; cd = codef[(pk.y >> 7) & 127];
        o0.y = (cd < 0.0f) ? -1.0f : cs;  o1.y = (cs < 0.0f) ? -1.0f : cd;
        cs = codef[pk.z & 127]; cd = codef[(pk.z >> 7) & 127];
        o0.z = (cd < 0.0f) ? -1.0f : cs;  o1.z = (cs < 0.0f) ? -1.0f : cd;
        cs = codef[pk.w & 127]; cd = codef[(pk.w >> 7) & 127];
        o0.w = (cd < 0.0f) ? -1.0f : cs;  o1.w = (cs < 0.0f) ? -1.0f : cd;
        e0out[t] = o0;
        e1out[t] = o1;
    }
    if (t + 256 < EPG4) {
        int q = t + 256;
        int4 pk = reinterpret_cast<const int4*>(packed)[q];
        float4 o0, o1; float cs, cd;
        cs = codef[pk.x & 127]; cd = codef[(pk.x >> 7) & 127];
        o0.x = (cd < 0.0f) ? -1.0f : cs;  o1.x = (cs < 0.0f) ? -1.0f : cd;
        cs = codef[pk.y & 127]; cd = codef[(pk.y >> 7) & 127];
        o0.y = (cd < 0.0f) ? -1.0f : cs;  o1.y = (cs < 0.0f) ? -1.0f : cd;
        cs = codef[pk.z & 127]; cd = codef[(pk.z >> 7) & 127];
        o0.z = (cd < 0.0f) ? -1.0f : cs;  o1.z = (cs < 0.0f) ? -1.0f : cd;
        cs = codef[pk.w & 127]; cd = codef[(pk.w >> 7) & 127];
        o0.w = (cd < 0.0f) ? -1.0f : cs;  o1.w = (cs < 0.0f) ? -1.0f : cd;
        e0out[q] = o0;
        e1out[q] = o1;
    }
}

extern "C" void kernel_launch(void* const* d_in, const int* in_sizes, int n_in,
                              void* d_out, int out_size)
{
    const float* x     = (const float*)d_in[0];
    const int*   ei    = (const int*)d_in[1];
    const float* theta = (const float*)d_in[3];
    float* out = (float*)d_out;

    int N = in_sizes[0] / F_DIM;   // 100000
    int E = in_sizes[1] / 2;       // 1600000
    int B = N / NPG;               // 1000

    sagpool_fused_kernel<<<B, TPB>>>(x, ei, theta, out, E, B);
}